// round 8
// baseline (speedup 1.0000x reference)
#include <cuda_runtime.h>
#include <cstdint>

// Fixed shapes from reference setup_inputs
#define BS   32
#define C    256
#define HW   4096          // 64*64
#define HID  32            // C / R
#define NPLANES (BS * C)   // 8192

#define GRID 512           // 16 CTAs per batch; one wave (4/SM guaranteed)
#define CPB  16            // CTAs per batch
#define PPC  16            // planes per CTA (2 per warp)

// Device-global scratch + sync (zero-init at load; self-reset each launch).
__device__ float             g_pooled[NPLANES];
__device__ float4            g_coef[NPLANES];     // (a0,a1,q0,q1) per plane
__device__ unsigned          g_cnt[BS];           // pool arrivals per batch
__device__ unsigned          g_done[BS];          // apply completions per batch
__device__ volatile int      g_flag[BS];          // coef-ready per batch

__global__ __launch_bounds__(256, 4) void fused_batchflag(
    const float* __restrict__ x,
    const float* __restrict__ w1, const float* __restrict__ b1,
    const float* __restrict__ w2, const float* __restrict__ b2,
    float* __restrict__ out)
{
    const int bid = blockIdx.x;
    const int b   = bid >> 4;          // batch
    const int s   = bid & 15;          // slot within batch
    const int t   = threadIdx.x;
    const int w   = t >> 5;            // warp 0..7
    const int l   = t & 31;            // lane
    const int pbase = b * C + s * PPC; // first of this CTA's 16 planes

    // ---------------- Phase 1: pool own 16 planes (2 per warp) ----------------
#pragma unroll
    for (int k = 0; k < 2; ++k) {
        const int p = pbase + 2 * w + k;
        const float4* __restrict__ x4 =
            reinterpret_cast<const float4*>(x) + (size_t)p * (HW / 4);
        float sum = 0.f;
#pragma unroll
        for (int it = 0; it < 4; ++it) {
            float4 v0 = x4[l + (it * 8 + 0) * 32];
            float4 v1 = x4[l + (it * 8 + 1) * 32];
            float4 v2 = x4[l + (it * 8 + 2) * 32];
            float4 v3 = x4[l + (it * 8 + 3) * 32];
            float4 v4 = x4[l + (it * 8 + 4) * 32];
            float4 v5 = x4[l + (it * 8 + 5) * 32];
            float4 v6 = x4[l + (it * 8 + 6) * 32];
            float4 v7 = x4[l + (it * 8 + 7) * 32];
            sum += ((v0.x + v0.y) + (v0.z + v0.w)) + ((v1.x + v1.y) + (v1.z + v1.w))
                 + ((v2.x + v2.y) + (v2.z + v2.w)) + ((v3.x + v3.y) + (v3.z + v3.w))
                 + ((v4.x + v4.y) + (v4.z + v4.w)) + ((v5.x + v5.y) + (v5.z + v5.w))
                 + ((v6.x + v6.y) + (v6.z + v6.w)) + ((v7.x + v7.y) + (v7.z + v7.w));
        }
#pragma unroll
        for (int o = 16; o > 0; o >>= 1) sum += __shfl_down_sync(0xffffffffu, sum, o);
        if (l == 0) g_pooled[p] = sum * (1.0f / (float)HW);
    }

    __syncthreads();
    __shared__ int s_last;
    if (t == 0) {
        __threadfence();                          // release g_pooled writes
        unsigned old = atomicAdd(&g_cnt[b], 1u);
        s_last = (old == CPB - 1);
    }
    __syncthreads();

    // ------------- Phase 2: last arriver computes batch coefficients -------------
    if (s_last) {
        __threadfence();                          // acquire peers' g_pooled
        __shared__ float sp[C];
        __shared__ float sh[HID];
        sp[t] = __ldcg(&g_pooled[b * C + t]);
        __syncthreads();

        if (t < HID) {
            float acc = b1[t];
            const float* __restrict__ w1r = w1 + t * C;
#pragma unroll 8
            for (int i = 0; i < C; ++i) acc = fmaf(sp[i], w1r[i], acc);
            sh[t] = fmaxf(acc, 0.f);
        }
        __syncthreads();

        {   // thread t -> channel t: 4 dots of length HID
            const int cc = t;
            float z00 = b2[2 * cc];
            float z01 = b2[2 * cc + 1];
            float z10 = b2[512 + 2 * cc];
            float z11 = b2[512 + 2 * cc + 1];
            const float* __restrict__ r00 = w2 + (size_t)(2 * cc) * HID;
            const float* __restrict__ r01 = w2 + (size_t)(2 * cc + 1) * HID;
            const float* __restrict__ r10 = w2 + (size_t)(512 + 2 * cc) * HID;
            const float* __restrict__ r11 = w2 + (size_t)(512 + 2 * cc + 1) * HID;
#pragma unroll
            for (int h = 0; h < HID; ++h) {
                const float hv = sh[h];
                z00 = fmaf(hv, r00[h], z00);
                z01 = fmaf(hv, r01[h], z01);
                z10 = fmaf(hv, r10[h], z10);
                z11 = fmaf(hv, r11[h], z11);
            }
            float4 cf;
            cf.x = 1.0f + tanhf(0.5f * z00);          // a0 = 1 + 1.0*delta
            cf.y =        tanhf(0.5f * z10);          // a1 = 0 + 1.0*delta
            cf.z = 1.0f + 0.5f * tanhf(0.5f * z01);   // q0 = 1 + 0.5*delta
            cf.w =        0.5f * tanhf(0.5f * z11);   // q1 = 0 + 0.5*delta
            g_coef[b * C + cc] = cf;
        }
        __syncthreads();
        __threadfence();                          // release g_coef
        if (t == 0) g_flag[b] = 1;
    }

    // ------------- Phase 3: wait for own batch only (all 16 CTAs resident) -------------
    if (t == 0) {
        while (g_flag[b] == 0) __nanosleep(64);
    }
    __syncthreads();
    __threadfence();                              // acquire g_coef

    // ------------- Phase 4: apply own 16 planes (reads likely L2-resident) -------------
#pragma unroll
    for (int k = 0; k < 2; ++k) {
        const int p = pbase + 2 * w + k;
        const float4 cf = __ldcg(&g_coef[p]);
        const float4* __restrict__ x4 =
            reinterpret_cast<const float4*>(x) + (size_t)p * (HW / 4);
        float4* __restrict__ o4 =
            reinterpret_cast<float4*>(out) + (size_t)p * (HW / 4);
#pragma unroll
        for (int it = 0; it < 4; ++it) {
            float4 v0 = __ldcs(&x4[l + (it * 8 + 0) * 32]);
            float4 v1 = __ldcs(&x4[l + (it * 8 + 1) * 32]);
            float4 v2 = __ldcs(&x4[l + (it * 8 + 2) * 32]);
            float4 v3 = __ldcs(&x4[l + (it * 8 + 3) * 32]);
            float4 v4 = __ldcs(&x4[l + (it * 8 + 4) * 32]);
            float4 v5 = __ldcs(&x4[l + (it * 8 + 5) * 32]);
            float4 v6 = __ldcs(&x4[l + (it * 8 + 6) * 32]);
            float4 v7 = __ldcs(&x4[l + (it * 8 + 7) * 32]);
#define APPLY_ST(v, idx)                                                      \
            {                                                                 \
                float4 r;                                                     \
                r.x = fmaxf(fmaf(v.x, cf.x, cf.z), fmaf(v.x, cf.y, cf.w));    \
                r.y = fmaxf(fmaf(v.y, cf.x, cf.z), fmaf(v.y, cf.y, cf.w));    \
                r.z = fmaxf(fmaf(v.z, cf.x, cf.z), fmaf(v.z, cf.y, cf.w));    \
                r.w = fmaxf(fmaf(v.w, cf.x, cf.z), fmaf(v.w, cf.y, cf.w));    \
                __stcs(&o4[l + (idx) * 32], r);                               \
            }
            APPLY_ST(v0, it * 8 + 0) APPLY_ST(v1, it * 8 + 1)
            APPLY_ST(v2, it * 8 + 2) APPLY_ST(v3, it * 8 + 3)
            APPLY_ST(v4, it * 8 + 4) APPLY_ST(v5, it * 8 + 5)
            APPLY_ST(v6, it * 8 + 6) APPLY_ST(v7, it * 8 + 7)
#undef APPLY_ST
        }
    }

    // ------------- Phase 5: self-reset sync state for graph replay -------------
    __syncthreads();
    if (t == 0) {
        unsigned old = atomicAdd(&g_done[b], 1u);
        if (old == CPB - 1) {      // all 16 CTAs passed the flag; safe to reset
            g_flag[b] = 0;
            g_cnt[b]  = 0u;
            g_done[b] = 0u;
        }
    }
}

extern "C" void kernel_launch(void* const* d_in, const int* in_sizes, int n_in,
                              void* d_out, int out_size) {
    const float* x  = (const float*)d_in[0];
    const float* w1 = (const float*)d_in[1];
    const float* b1 = (const float*)d_in[2];
    const float* w2 = (const float*)d_in[3];
    const float* b2 = (const float*)d_in[4];
    float* out = (float*)d_out;

    fused_batchflag<<<GRID, 256>>>(x, w1, b1, w2, b2, out);
}